// round 7
// baseline (speedup 1.0000x reference)
#include <cuda_runtime.h>
#include <cuda_bf16.h>
#include <math.h>
#include <stdint.h>

#define Bn 512
#define Tn 512
#define NBLK 128
#define NTHR 512

// ---- dynamic SMEM layout (bytes) ----
#define OFF_HHI(b) ((b) * 32768)            // h_hi chunk buf: 128 rows x 128B (SW128)
#define OFF_HLO(b) ((b) * 32768 + 16384)    // h_lo chunk buf
#define OFF_WHI    65536                    // W_hi tile: 512 k-rows x 128B (SW128) = 64KB
#define OFF_WLO    131072                   // W_lo tile = 64KB
#define OFF_WIH    196608                   // 64 floats
#define OFF_BIAS   196864                   // 64 floats
#define OFF_SNAP   197120                   // 10 uints: flag bases [0..7], rd bases [8..9]
#define SMEM_BYTES 197184
// epilogue bounce regions (reuse buf0, free at that point)
#define BOUNCE_HH  0                        // 128x16 bf16 = 4KB
#define BOUNCE_HL  4096                     // 4KB
#define BOUNCE_HF  16384                    // 128x16 f32 = 8KB (final step only)

static __device__ __forceinline__ uint32_t sw128(uint32_t x) { return x ^ ((x >> 3) & 0x70); }

// ---- global scratch (no cudaMalloc allowed) ----
__device__ __nv_bfloat16 g_hh[2][Bn][512];   // h hi, ping-pong, [batch][hidden]
__device__ __nv_bfloat16 g_hl[2][Bn][512];   // h lo
__device__ float g_seqT[Tn][Bn];
__device__ float g_hf[Bn][512];              // final fp32 h for MLP head
__device__ unsigned g_count = 0;
__device__ volatile unsigned g_gen = 0;
__device__ unsigned g_flag[4][8];            // producer counts per (batch grp, k-chunk)
__device__ unsigned g_rd[4][2];              // reader-done counts per (batch grp, buf parity)

__device__ __forceinline__ uint32_t smem_u32(const void* p) {
    uint32_t a;
    asm("{ .reg .u64 t; cvta.to.shared.u64 t, %1; cvt.u32.u64 %0, t; }" : "=r"(a) : "l"(p));
    return a;
}
__device__ __forceinline__ void ldsm_x4(uint32_t* r, uint32_t addr) {
    asm volatile("ldmatrix.sync.aligned.m8n8.x4.shared.b16 {%0,%1,%2,%3}, [%4];"
                 : "=r"(r[0]), "=r"(r[1]), "=r"(r[2]), "=r"(r[3]) : "r"(addr));
}
__device__ __forceinline__ void ldsm_x4_t(uint32_t* r, uint32_t addr) {
    asm volatile("ldmatrix.sync.aligned.m8n8.x4.trans.shared.b16 {%0,%1,%2,%3}, [%4];"
                 : "=r"(r[0]), "=r"(r[1]), "=r"(r[2]), "=r"(r[3]) : "r"(addr));
}
__device__ __forceinline__ void mma_bf16(float* d, const uint32_t* a, const uint32_t* b) {
    asm volatile(
        "mma.sync.aligned.m16n8k16.row.col.f32.bf16.bf16.f32 "
        "{%0,%1,%2,%3}, {%4,%5,%6,%7}, {%8,%9}, {%0,%1,%2,%3};"
        : "+f"(d[0]), "+f"(d[1]), "+f"(d[2]), "+f"(d[3])
        : "r"(a[0]), "r"(a[1]), "r"(a[2]), "r"(a[3]), "r"(b[0]), "r"(b[1]));
}
__device__ __forceinline__ void cp16(uint32_t dst, const void* src) {
    asm volatile("cp.async.cg.shared.global [%0], [%1], 16;"
                 :: "r"(dst), "l"(__cvta_generic_to_global(src)) : "memory");
}
__device__ __forceinline__ void cp_commit() {
    asm volatile("cp.async.commit_group;" ::: "memory");
}
__device__ __forceinline__ void cp_wait0() {
    asm volatile("cp.async.wait_group 0;" ::: "memory");
}

__device__ __forceinline__ void grid_sync(unsigned target) {
    __syncthreads();
    if (threadIdx.x == 0) {
        __threadfence();
        unsigned old = atomicAdd(&g_count, 1u);
        if (old == NBLK - 1) {
            g_count = 0;
            __threadfence();
            g_gen = target;
        } else {
            while (g_gen != target) { }
            __threadfence();
        }
    }
    __syncthreads();
}

__device__ __forceinline__ float sigf(float x)  { return __fdividef(1.0f, 1.0f + __expf(-x)); }
__device__ __forceinline__ float tanhf_(float x){ return __fdividef(2.0f, 1.0f + __expf(-2.0f * x)) - 1.0f; }

__global__ __launch_bounds__(NTHR, 1)
void lstm_tc(const float* __restrict__ seq,
             const float* __restrict__ Wih,
             const float* __restrict__ Whh,
             const float* __restrict__ bih,
             const float* __restrict__ bhh)
{
    extern __shared__ char smem[];
    __shared__ unsigned s_base;
    const uint32_t sb = smem_u32(smem);
    const int tid  = threadIdx.x;
    const int w    = tid >> 5;
    const int lane = tid & 31;
    const int bi   = blockIdx.x >> 5;   // batch tile 0..3
    const int ji   = blockIdx.x & 31;   // hidden-slice tile 0..31 (16 units each)
    const int b0   = bi * 128;
    const int j0   = ji * 16;

    if (tid == 0) s_base = g_gen;
    // snapshot monotonic counters (stable until every CTA passes the initial barrier)
    unsigned* snap = (unsigned*)(smem + OFF_SNAP);
    if (tid < 8)  snap[tid] = g_flag[bi][tid];
    if (tid >= 8 && tid < 10) snap[tid] = g_rd[bi][tid - 8];

    // ---- W_hh tile -> SMEM, bf16 hi/lo, k-major [k][n], SW128 swizzle ----
    for (int idx = tid; idx < 64 * 512; idx += NTHR) {
        int n = idx >> 9, k = idx & 511;
        int row = (n & 3) * 512 + j0 + (n >> 2);
        float wv = Whh[(size_t)row * 512 + k];
        __nv_bfloat16 whi = __float2bfloat16(wv);
        __nv_bfloat16 wlo = __float2bfloat16(wv - __bfloat162float(whi));
        uint32_t so = sw128((uint32_t)k * 128 + n * 2);
        *(__nv_bfloat16*)(smem + OFF_WHI + so) = whi;
        *(__nv_bfloat16*)(smem + OFF_WLO + so) = wlo;
    }
    if (tid < 64) {
        int jl = tid >> 2, g = tid & 3;
        int row = g * 512 + j0 + jl;
        ((float*)(smem + OFF_WIH))[tid]  = Wih[row];
        ((float*)(smem + OFF_BIAS))[tid] = bih[row] + bhh[row];
    }
    // zero h0 (buffer 0) and transpose sequence
    {
        int base = blockIdx.x * 2048;
        #pragma unroll
        for (int i = 0; i < 4; ++i) {
            int idx = base + i * NTHR + tid;
            ((__nv_bfloat16*)g_hh)[idx] = __float2bfloat16(0.0f);
            ((__nv_bfloat16*)g_hl)[idx] = __float2bfloat16(0.0f);
            int b = idx >> 9, t = idx & 511;
            g_seqT[t][b] = seq[idx];
        }
    }
    grid_sync(s_base + 1);

    // ---- per-lane constants ----
    const int wm = w & 3;
    const int wn = w >> 2;
    const int l15 = lane & 15;
    const int lb  = lane >> 4;
    const uint32_t a_row  = (uint32_t)(wm * 32 + l15);
    const uint32_t a_xm   = a_row & 7;
    const uint32_t a_base = sb + a_row * 128;
    const uint32_t b_col16 = (uint32_t)(((wn * 2 + lb) ^ (l15 & 7)));
    const uint32_t b_base  = sb + OFF_WHI + (uint32_t)l15 * 128 + b_col16 * 16;

    // staging (cp.async dst): thread -> row tid>>2, 32B quarter tid&3
    const int sm_r = tid >> 2, sq = tid & 3;
    const uint32_t sts_off  = sw128((uint32_t)sm_r * 128 + sq * 32);
    const uint32_t sts_off2 = sts_off ^ 16;  // sw128(x+16) == sw128(x) ^ 16 (bit4 of raw x is 0)

    const float* wih_s  = (const float*)(smem + OFF_WIH);
    const float* bias_s = (const float*)(smem + OFF_BIAS);
    float bw_a[2], bw_b[2], wi_a[2], wi_b[2];
    #pragma unroll
    for (int nt = 0; nt < 2; ++nt) {
        int ca = wn * 16 + nt * 8 + (lane & 3) * 2;
        bw_a[nt] = bias_s[ca];     bw_b[nt] = bias_s[ca + 1];
        wi_a[nt] = wih_s[ca];      wi_b[nt] = wih_s[ca + 1];
    }
    const int q = lane & 1;
    const int rowm0 = wm * 32 + (lane >> 2);
    float cst[4] = {0.f, 0.f, 0.f, 0.f};

    const unsigned fb0 = snap[0];
    const unsigned rdb0 = snap[8], rdb1 = snap[9];
    volatile unsigned* flags = (volatile unsigned*)&g_flag[bi][0];
    volatile unsigned* rds   = (volatile unsigned*)&g_rd[bi][0];
    const int mychunk = ji >> 2;   // producer flag index

    for (int t = 0; t < Tn; ++t) {
        const int rb = t & 1, nb = rb ^ 1;
        const unsigned need = 4u * (unsigned)t;

        // init accumulators with bias + x*W_ih (mma accumulates on top)
        float acc[2][2][4];
        #pragma unroll
        for (int mt = 0; mt < 2; ++mt) {
            float svA = g_seqT[t][b0 + rowm0 + mt * 16];
            float svB = g_seqT[t][b0 + rowm0 + mt * 16 + 8];
            #pragma unroll
            for (int nt = 0; nt < 2; ++nt) {
                acc[mt][nt][0] = fmaf(svA, wi_a[nt], bw_a[nt]);
                acc[mt][nt][1] = fmaf(svA, wi_b[nt], bw_b[nt]);
                acc[mt][nt][2] = fmaf(svB, wi_a[nt], bw_a[nt]);
                acc[mt][nt][3] = fmaf(svB, wi_b[nt], bw_b[nt]);
            }
        }

        // prologue: wait for chunk 0's 4 producers, stage it into buf 0
        while (flags[0] - fb0 < need) { }
        __threadfence();
        {
            const __nv_bfloat16* sh = &g_hh[rb][b0 + sm_r][sq * 16];
            const __nv_bfloat16* sl = &g_hl[rb][b0 + sm_r][sq * 16];
            cp16(sb + OFF_HHI(0) + sts_off,  sh);
            cp16(sb + OFF_HHI(0) + sts_off2, sh + 8);
            cp16(sb + OFF_HLO(0) + sts_off,  sl);
            cp16(sb + OFF_HLO(0) + sts_off2, sl + 8);
            cp_commit();
        }
        unsigned fv = flags[1];   // prefetched flag value for chunk 1

        #pragma unroll 1
        for (int kc = 0; kc < 8; ++kc) {
            cp_wait0();
            __syncthreads();      // chunk kc visible to all; prior reads of other buf done
            if (kc < 7) {
                if (fv - snap[kc + 1] < need) {
                    while (flags[kc + 1] - snap[kc + 1] < need) { }
                }
                __threadfence();
                const int nbuf = (kc + 1) & 1;
                const __nv_bfloat16* sh = &g_hh[rb][b0 + sm_r][(kc + 1) * 64 + sq * 16];
                const __nv_bfloat16* sl = &g_hl[rb][b0 + sm_r][(kc + 1) * 64 + sq * 16];
                cp16(sb + OFF_HHI(nbuf) + sts_off,  sh);
                cp16(sb + OFF_HHI(nbuf) + sts_off2, sh + 8);
                cp16(sb + OFF_HLO(nbuf) + sts_off,  sl);
                cp16(sb + OFF_HLO(nbuf) + sts_off2, sl + 8);
                cp_commit();
                if (kc < 6) fv = flags[kc + 2];
            }

            const uint32_t abuf = a_base + OFF_HHI(kc & 1);
            const uint32_t bk   = b_base + (uint32_t)kc * 8192;
            #pragma unroll
            for (int kq = 0; kq < 4; ++kq) {
                const uint32_t acol = (uint32_t)(((kq * 2 + lb) ^ a_xm)) << 4;
                uint32_t ah0[4], ah1[4], al0[4], al1[4], bh[4], bl[4];
                ldsm_x4(ah0, abuf + acol);
                ldsm_x4(ah1, abuf + 2048 + acol);
                ldsm_x4(al0, abuf + 16384 + acol);
                ldsm_x4(al1, abuf + 16384 + 2048 + acol);
                ldsm_x4_t(bh, bk + (uint32_t)kq * 2048);
                ldsm_x4_t(bl, bk + (uint32_t)kq * 2048 + 65536);
                mma_bf16(acc[0][0], ah0, bh);     mma_bf16(acc[0][1], ah0, bh + 2);
                mma_bf16(acc[1][0], ah1, bh);     mma_bf16(acc[1][1], ah1, bh + 2);
                mma_bf16(acc[0][0], al0, bh);     mma_bf16(acc[0][1], al0, bh + 2);
                mma_bf16(acc[1][0], al1, bh);     mma_bf16(acc[1][1], al1, bh + 2);
                mma_bf16(acc[0][0], ah0, bl);     mma_bf16(acc[0][1], ah0, bl + 2);
                mma_bf16(acc[1][0], ah1, bl);     mma_bf16(acc[1][1], ah1, bl + 2);
            }
        }

        __syncthreads();   // all copies landed (each thread did wait0) & all reads done
        if (tid == 0) atomicAdd(&g_rd[bi][rb], 1u);   // this CTA finished reading buf rb

        // ---- LSTM cell epilogue: lane pairs exchange (i,f)<->(g,o) ----
        #pragma unroll
        for (int mt = 0; mt < 2; ++mt) {
            #pragma unroll
            for (int nt = 0; nt < 2; ++nt) {
                float x0 = __shfl_xor_sync(0xffffffffu, acc[mt][nt][0], 1);
                float x1 = __shfl_xor_sync(0xffffffffu, acc[mt][nt][1], 1);
                float x2 = __shfl_xor_sync(0xffffffffu, acc[mt][nt][2], 1);
                float x3 = __shfl_xor_sync(0xffffffffu, acc[mt][nt][3], 1);
                float gi, gf, gg, go;
                int rowl;
                if (q == 0) { gi = acc[mt][nt][0]; gf = acc[mt][nt][1]; gg = x0; go = x1;
                              rowl = rowm0 + mt * 16; }
                else        { gi = x2; gf = x3; gg = acc[mt][nt][2]; go = acc[mt][nt][3];
                              rowl = rowm0 + mt * 16 + 8; }
                const int ci = mt * 2 + nt;
                cst[ci] = sigf(gf) * cst[ci] + sigf(gi) * tanhf_(gg);
                float h = sigf(go) * tanhf_(cst[ci]);
                int ul = wn * 4 + nt * 2 + ((lane & 3) >> 1);
                __nv_bfloat16 hhi = __float2bfloat16(h);
                __nv_bfloat16 hlo = __float2bfloat16(h - __bfloat162float(hhi));
                *(__nv_bfloat16*)(smem + BOUNCE_HH + rowl * 32 + ul * 2) = hhi;
                *(__nv_bfloat16*)(smem + BOUNCE_HL + rowl * 32 + ul * 2) = hlo;
                if (t == Tn - 1)
                    *(float*)(smem + BOUNCE_HF + rowl * 64 + ul * 4) = h;
            }
        }
        __syncthreads();

        if (t < Tn - 1) {
            // writer permission: all group readers of buf nb (parity) must be done
            const unsigned rneed = 32u * (unsigned)((t + 1) >> 1);
            const unsigned rbase = nb ? rdb1 : rdb0;
            if (rneed) { while (rds[nb] - rbase < rneed) { } __threadfence(); }
            unsigned long long hv = *(unsigned long long*)(smem + BOUNCE_HH + sm_r * 32 + sq * 8);
            unsigned long long lv = *(unsigned long long*)(smem + BOUNCE_HL + sm_r * 32 + sq * 8);
            *(unsigned long long*)&g_hh[nb][b0 + sm_r][j0 + sq * 4] = hv;
            *(unsigned long long*)&g_hl[nb][b0 + sm_r][j0 + sq * 4] = lv;
            __syncthreads();   // all STGs issued & bounce reads done (also orders for release)
            if (tid == 0) { __threadfence(); atomicAdd(&g_flag[bi][mychunk], 1u); }
        } else {
            float4 f4 = *(float4*)(smem + BOUNCE_HF + sm_r * 64 + sq * 16);
            *(float4*)&g_hf[b0 + sm_r][j0 + sq * 4] = f4;
            __syncthreads();
        }
        // next prologue's cp.async into buf0 is safe: bounce reads completed above
    }
}

__global__ __launch_bounds__(256)
void mlp_head(const float* __restrict__ fc1w, const float* __restrict__ fc1b,
              const float* __restrict__ fc2w, const float* __restrict__ fc2b,
              float* __restrict__ out)
{
    __shared__ float hcol[512];
    __shared__ float z[256];
    const int b = blockIdx.x;
    const int tid = threadIdx.x;

    hcol[tid]       = g_hf[b][tid];
    hcol[tid + 256] = g_hf[b][tid + 256];
    __syncthreads();

    float acc = fc1b[tid];
    const float4* w4 = (const float4*)(fc1w + (size_t)tid * 512);
    const float4* h4 = (const float4*)hcol;
    #pragma unroll 4
    for (int k = 0; k < 128; ++k) {
        float4 wv = w4[k], hv = h4[k];
        acc = fmaf(wv.x, hv.x, acc); acc = fmaf(wv.y, hv.y, acc);
        acc = fmaf(wv.z, hv.z, acc); acc = fmaf(wv.w, hv.w, acc);
    }
    z[tid] = fmaxf(acc, 0.0f);
    __syncthreads();

    if (tid < 28) {
        float o = fc2b[tid];
        const float4* w4b = (const float4*)(fc2w + (size_t)tid * 256);
        const float4* z4  = (const float4*)z;
        #pragma unroll 4
        for (int k = 0; k < 64; ++k) {
            float4 wv = w4b[k], zz = z4[k];
            o = fmaf(wv.x, zz.x, o); o = fmaf(wv.y, zz.y, o);
            o = fmaf(wv.z, zz.z, o); o = fmaf(wv.w, zz.w, o);
        }
        out[b * 28 + tid] = o;
    }
}

extern "C" void kernel_launch(void* const* d_in, const int* in_sizes, int n_in,
                              void* d_out, int out_size) {
    const float* seq  = (const float*)d_in[0];
    const float* Wih  = (const float*)d_in[1];
    const float* Whh  = (const float*)d_in[2];
    const float* bih  = (const float*)d_in[3];
    const float* bhh  = (const float*)d_in[4];
    const float* fc1w = (const float*)d_in[5];
    const float* fc1b = (const float*)d_in[6];
    const float* fc2w = (const float*)d_in[7];
    const float* fc2b = (const float*)d_in[8];
    float* out = (float*)d_out;

    cudaFuncSetAttribute(lstm_tc, cudaFuncAttributeMaxDynamicSharedMemorySize, SMEM_BYTES);
    lstm_tc<<<NBLK, NTHR, SMEM_BYTES>>>(seq, Wih, Whh, bih, bhh);
    mlp_head<<<Bn, 256>>>(fc1w, fc1b, fc2w, fc2b, out);
}

// round 8
// speedup vs baseline: 1.9670x; 1.9670x over previous
#include <cuda_runtime.h>
#include <cuda_fp16.h>
#include <math.h>
#include <stdint.h>

#define Bn 512
#define Tn 512
#define NBLK 128
#define NTHR 512

// ---- dynamic SMEM layout (bytes) ----
#define OFF_H(b)   ((b) * 16384)            // h chunk buf (fp16): 128 rows x 128B (SW128)
#define OFF_WHI    32768                    // W_hi tile: 512 k-rows x 128B (SW128) = 64KB
#define OFF_WLO    98304                    // W_lo tile = 64KB  (OFF_WHI + 65536)
#define OFF_WIH    163840                   // 64 floats
#define OFF_BIAS   164096                   // 64 floats
#define SMEM_BYTES 164352
// epilogue bounce regions (reuse buf0, free at that point)
#define BOUNCE_HH  0                        // 128x16 fp16 = 4KB
#define BOUNCE_HF  4096                     // 128x16 f32 = 8KB (final step only)

static __device__ __forceinline__ uint32_t sw128(uint32_t x) { return x ^ ((x >> 3) & 0x70); }

// ---- global scratch (no cudaMalloc allowed) ----
__device__ __half g_hh[2][Bn][512];          // h (fp16), ping-pong, [batch][hidden]
__device__ float g_seqT[Tn][Bn];
__device__ float g_hf[Bn][512];              // final fp32 h for MLP head
__device__ unsigned g_count = 0;
__device__ volatile unsigned g_gen = 0;

__device__ __forceinline__ uint32_t smem_u32(const void* p) {
    uint32_t a;
    asm("{ .reg .u64 t; cvta.to.shared.u64 t, %1; cvt.u32.u64 %0, t; }" : "=r"(a) : "l"(p));
    return a;
}
__device__ __forceinline__ void ldsm_x4(uint32_t* r, uint32_t addr) {
    asm volatile("ldmatrix.sync.aligned.m8n8.x4.shared.b16 {%0,%1,%2,%3}, [%4];"
                 : "=r"(r[0]), "=r"(r[1]), "=r"(r[2]), "=r"(r[3]) : "r"(addr));
}
__device__ __forceinline__ void ldsm_x4_t(uint32_t* r, uint32_t addr) {
    asm volatile("ldmatrix.sync.aligned.m8n8.x4.trans.shared.b16 {%0,%1,%2,%3}, [%4];"
                 : "=r"(r[0]), "=r"(r[1]), "=r"(r[2]), "=r"(r[3]) : "r"(addr));
}
__device__ __forceinline__ void mma_f16(float* d, const uint32_t* a, const uint32_t* b) {
    asm volatile(
        "mma.sync.aligned.m16n8k16.row.col.f32.f16.f16.f32 "
        "{%0,%1,%2,%3}, {%4,%5,%6,%7}, {%8,%9}, {%0,%1,%2,%3};"
        : "+f"(d[0]), "+f"(d[1]), "+f"(d[2]), "+f"(d[3])
        : "r"(a[0]), "r"(a[1]), "r"(a[2]), "r"(a[3]), "r"(b[0]), "r"(b[1]));
}
__device__ __forceinline__ void cp16(uint32_t dst, const void* src) {
    asm volatile("cp.async.cg.shared.global [%0], [%1], 16;"
                 :: "r"(dst), "l"(__cvta_generic_to_global(src)) : "memory");
}
__device__ __forceinline__ void cp_commit() {
    asm volatile("cp.async.commit_group;" ::: "memory");
}
__device__ __forceinline__ void cp_wait0() {
    asm volatile("cp.async.wait_group 0;" ::: "memory");
}

__device__ __forceinline__ void grid_sync(unsigned target) {
    __syncthreads();
    if (threadIdx.x == 0) {
        __threadfence();
        unsigned old = atomicAdd(&g_count, 1u);
        if (old == NBLK - 1) {
            g_count = 0;
            __threadfence();
            g_gen = target;
        } else {
            while (g_gen != target) { }
            __threadfence();
        }
    }
    __syncthreads();
}

__device__ __forceinline__ float sigf(float x)  { return __fdividef(1.0f, 1.0f + __expf(-x)); }
__device__ __forceinline__ float tanhf_(float x){ return __fdividef(2.0f, 1.0f + __expf(-2.0f * x)) - 1.0f; }

__global__ __launch_bounds__(NTHR, 1)
void lstm_tc(const float* __restrict__ seq,
             const float* __restrict__ Wih,
             const float* __restrict__ Whh,
             const float* __restrict__ bih,
             const float* __restrict__ bhh)
{
    extern __shared__ char smem[];
    __shared__ unsigned s_base;
    const uint32_t sb = smem_u32(smem);
    const int tid  = threadIdx.x;
    const int w    = tid >> 5;
    const int lane = tid & 31;
    const int bi   = blockIdx.x >> 5;   // batch tile 0..3
    const int ji   = blockIdx.x & 31;   // hidden-slice tile 0..31 (16 units each)
    const int b0   = bi * 128;
    const int j0   = ji * 16;

    if (tid == 0) s_base = g_gen;

    // ---- W_hh tile -> SMEM, fp16 hi/lo, k-major [k][n], SW128 swizzle ----
    // local col n = jl*4+g  <->  global W row = g*512 + j0 + jl
    for (int idx = tid; idx < 64 * 512; idx += NTHR) {
        int n = idx >> 9, k = idx & 511;
        int row = (n & 3) * 512 + j0 + (n >> 2);
        float wv = Whh[(size_t)row * 512 + k];
        __half whi = __float2half_rn(wv);
        __half wlo = __float2half_rn(wv - __half2float(whi));
        uint32_t so = sw128((uint32_t)k * 128 + n * 2);
        *(__half*)(smem + OFF_WHI + so) = whi;
        *(__half*)(smem + OFF_WLO + so) = wlo;
    }
    if (tid < 64) {
        int jl = tid >> 2, g = tid & 3;
        int row = g * 512 + j0 + jl;
        ((float*)(smem + OFF_WIH))[tid]  = Wih[row];
        ((float*)(smem + OFF_BIAS))[tid] = bih[row] + bhh[row];
    }
    // zero h0 (buffer 0) and transpose sequence
    {
        int base = blockIdx.x * 2048;
        #pragma unroll
        for (int i = 0; i < 4; ++i) {
            int idx = base + i * NTHR + tid;
            ((__half*)g_hh)[idx] = __float2half_rn(0.0f);
            int b = idx >> 9, t = idx & 511;
            g_seqT[t][b] = seq[idx];
        }
    }
    grid_sync(s_base + 1);
    const unsigned base_gen = s_base;

    // ---- per-lane constants ----
    const int wm = w & 3;                // batch quadrant of warp (m32)
    const int wn = w >> 2;               // gate-col quadrant (n16)
    const int l15 = lane & 15;
    const int lb  = lane >> 4;
    const uint32_t a_row  = (uint32_t)(wm * 32 + l15);
    const uint32_t a_xm   = a_row & 7;
    const uint32_t a_base = sb + a_row * 128;
    const uint32_t b_col16 = (uint32_t)(((wn * 2 + lb) ^ (l15 & 7)));
    const uint32_t b_base  = sb + OFF_WHI + (uint32_t)l15 * 128 + b_col16 * 16;

    // staging (cp.async dst): thread -> row tid>>2, 32B quarter tid&3
    const int sm_r = tid >> 2, sq = tid & 3;
    const uint32_t sts_off  = sw128((uint32_t)sm_r * 128 + sq * 32);
    const uint32_t sts_off2 = sts_off ^ 16;  // sw128(x+16) == sw128(x) ^ 16 (bit4 of raw x is 0)

    const float* wih_s  = (const float*)(smem + OFF_WIH);
    const float* bias_s = (const float*)(smem + OFF_BIAS);
    float bw_a[2], bw_b[2], wi_a[2], wi_b[2];
    #pragma unroll
    for (int nt = 0; nt < 2; ++nt) {
        int ca = wn * 16 + nt * 8 + (lane & 3) * 2;
        bw_a[nt] = bias_s[ca];     bw_b[nt] = bias_s[ca + 1];
        wi_a[nt] = wih_s[ca];      wi_b[nt] = wih_s[ca + 1];
    }
    const int q = lane & 1;
    const int rowm0 = wm * 32 + (lane >> 2);
    float cst[4] = {0.f, 0.f, 0.f, 0.f};

    for (int t = 0; t < Tn; ++t) {
        const int rb = t & 1, nb = rb ^ 1;

        // init accumulators with bias + x*W_ih (mma accumulates on top)
        float acc[2][2][4];
        #pragma unroll
        for (int mt = 0; mt < 2; ++mt) {
            float svA = g_seqT[t][b0 + rowm0 + mt * 16];
            float svB = g_seqT[t][b0 + rowm0 + mt * 16 + 8];
            #pragma unroll
            for (int nt = 0; nt < 2; ++nt) {
                acc[mt][nt][0] = fmaf(svA, wi_a[nt], bw_a[nt]);
                acc[mt][nt][1] = fmaf(svA, wi_b[nt], bw_b[nt]);
                acc[mt][nt][2] = fmaf(svB, wi_a[nt], bw_a[nt]);
                acc[mt][nt][3] = fmaf(svB, wi_b[nt], bw_b[nt]);
            }
        }

        // stage chunk 0 into buf 0 (h for this step is globally visible after barrier)
        {
            const __half* sh = &g_hh[rb][b0 + sm_r][sq * 16];
            cp16(sb + OFF_H(0) + sts_off,  sh);
            cp16(sb + OFF_H(0) + sts_off2, sh + 8);
            cp_commit();
        }

        #pragma unroll 1
        for (int kc = 0; kc < 8; ++kc) {
            cp_wait0();
            __syncthreads();      // chunk kc visible to all; prior reads of other buf done
            if (kc < 7) {
                const int nbuf = (kc + 1) & 1;
                const __half* sh = &g_hh[rb][b0 + sm_r][(kc + 1) * 64 + sq * 16];
                cp16(sb + OFF_H(nbuf) + sts_off,  sh);
                cp16(sb + OFF_H(nbuf) + sts_off2, sh + 8);
                cp_commit();
            }

            const uint32_t abuf = a_base + OFF_H(kc & 1);
            const uint32_t bk   = b_base + (uint32_t)kc * 8192;
            #pragma unroll
            for (int kq = 0; kq < 4; ++kq) {
                const uint32_t acol = (uint32_t)(((kq * 2 + lb) ^ a_xm)) << 4;
                uint32_t ah0[4], ah1[4], bh[4], bl[4];
                ldsm_x4(ah0, abuf + acol);                       // A m16 #0, k16
                ldsm_x4(ah1, abuf + 2048 + acol);                // A m16 #1
                ldsm_x4_t(bh, bk + (uint32_t)kq * 2048);         // W_hi (k16 x n16)
                ldsm_x4_t(bl, bk + (uint32_t)kq * 2048 + 65536); // W_lo
                // 8 HMMA: A*(W_hi) + A*(W_lo)  (W to ~22 bits, h fp16)
                mma_f16(acc[0][0], ah0, bh);   mma_f16(acc[0][1], ah0, bh + 2);
                mma_f16(acc[1][0], ah1, bh);   mma_f16(acc[1][1], ah1, bh + 2);
                mma_f16(acc[0][0], ah0, bl);   mma_f16(acc[0][1], ah0, bl + 2);
                mma_f16(acc[1][0], ah1, bl);   mma_f16(acc[1][1], ah1, bl + 2);
            }
        }

        __syncthreads();   // all chunk reads done -> buf0 reusable as bounce

        // ---- LSTM cell epilogue: lane pairs exchange (i,f)<->(g,o) ----
        #pragma unroll
        for (int mt = 0; mt < 2; ++mt) {
            #pragma unroll
            for (int nt = 0; nt < 2; ++nt) {
                float x0 = __shfl_xor_sync(0xffffffffu, acc[mt][nt][0], 1);
                float x1 = __shfl_xor_sync(0xffffffffu, acc[mt][nt][1], 1);
                float x2 = __shfl_xor_sync(0xffffffffu, acc[mt][nt][2], 1);
                float x3 = __shfl_xor_sync(0xffffffffu, acc[mt][nt][3], 1);
                float gi, gf, gg, go;
                int rowl;
                if (q == 0) { gi = acc[mt][nt][0]; gf = acc[mt][nt][1]; gg = x0; go = x1;
                              rowl = rowm0 + mt * 16; }
                else        { gi = x2; gf = x3; gg = acc[mt][nt][2]; go = acc[mt][nt][3];
                              rowl = rowm0 + mt * 16 + 8; }
                const int ci = mt * 2 + nt;
                cst[ci] = sigf(gf) * cst[ci] + sigf(gi) * tanhf_(gg);
                float h = sigf(go) * tanhf_(cst[ci]);
                int ul = wn * 4 + nt * 2 + ((lane & 3) >> 1);
                *(__half*)(smem + BOUNCE_HH + rowl * 32 + ul * 2) = __float2half_rn(h);
                if (t == Tn - 1)
                    *(float*)(smem + BOUNCE_HF + rowl * 64 + ul * 4) = h;
            }
        }
        __syncthreads();
        // coalesced write-out of this CTA's 128x16 h slice
        if (t < Tn - 1) {
            unsigned long long hv = *(unsigned long long*)(smem + BOUNCE_HH + sm_r * 32 + sq * 8);
            *(unsigned long long*)&g_hh[nb][b0 + sm_r][j0 + sq * 4] = hv;
        } else {
            float4 f4 = *(float4*)(smem + BOUNCE_HF + sm_r * 64 + sq * 16);
            *(float4*)&g_hf[b0 + sm_r][j0 + sq * 4] = f4;
        }
        grid_sync(base_gen + 2 + t);
    }
}

__global__ __launch_bounds__(256)
void mlp_head(const float* __restrict__ fc1w, const float* __restrict__ fc1b,
              const float* __restrict__ fc2w, const float* __restrict__ fc2b,
              float* __restrict__ out)
{
    __shared__ float hcol[512];
    __shared__ float z[256];
    const int b = blockIdx.x;
    const int tid = threadIdx.x;

    hcol[tid]       = g_hf[b][tid];
    hcol[tid + 256] = g_hf[b][tid + 256];
    __syncthreads();

    float acc = fc1b[tid];
    const float4* w4 = (const float4*)(fc1w + (size_t)tid * 512);
    const float4* h4 = (const float4*)hcol;
    #pragma unroll 4
    for (int k = 0; k < 128; ++k) {
        float4 wv = w4[k], hv = h4[k];
        acc = fmaf(wv.x, hv.x, acc); acc = fmaf(wv.y, hv.y, acc);
        acc = fmaf(wv.z, hv.z, acc); acc = fmaf(wv.w, hv.w, acc);
    }
    z[tid] = fmaxf(acc, 0.0f);
    __syncthreads();

    if (tid < 28) {
        float o = fc2b[tid];
        const float4* w4b = (const float4*)(fc2w + (size_t)tid * 256);
        const float4* z4  = (const float4*)z;
        #pragma unroll 4
        for (int k = 0; k < 64; ++k) {
            float4 wv = w4b[k], zz = z4[k];
            o = fmaf(wv.x, zz.x, o); o = fmaf(wv.y, zz.y, o);
            o = fmaf(wv.z, zz.z, o); o = fmaf(wv.w, zz.w, o);
        }
        out[b * 28 + tid] = o;
    }
}

extern "C" void kernel_launch(void* const* d_in, const int* in_sizes, int n_in,
                              void* d_out, int out_size) {
    const float* seq  = (const float*)d_in[0];
    const float* Wih  = (const float*)d_in[1];
    const float* Whh  = (const float*)d_in[2];
    const float* bih  = (const float*)d_in[3];
    const float* bhh  = (const float*)d_in[4];
    const float* fc1w = (const float*)d_in[5];
    const float* fc1b = (const float*)d_in[6];
    const float* fc2w = (const float*)d_in[7];
    const float* fc2b = (const float*)d_in[8];
    float* out = (float*)d_out;

    cudaFuncSetAttribute(lstm_tc, cudaFuncAttributeMaxDynamicSharedMemorySize, SMEM_BYTES);
    lstm_tc<<<NBLK, NTHR, SMEM_BYTES>>>(seq, Wih, Whh, bih, bhh);
    mlp_head<<<Bn, 256>>>(fc1w, fc1b, fc2w, fc2b, out);
}

// round 9
// speedup vs baseline: 2.3542x; 1.1969x over previous
#include <cuda_runtime.h>
#include <cuda_fp16.h>
#include <math.h>
#include <stdint.h>

#define Bn 512
#define Tn 512
#define NBLK 128
#define NTHR 512

// ---- dynamic SMEM layout (bytes) ----
#define OFF_H(b)   ((b) * 16384)            // h chunk buf (fp16): 128 rows x 128B (SW128)
#define OFF_W      32768                    // W tile (fp16): 512 k-rows x 128B (SW128) = 64KB
#define OFF_WIH    98304                    // 64 floats
#define OFF_BIAS   98560                    // 64 floats
#define SMEM_BYTES 98816
// epilogue bounce regions (reuse buf0, free at that point)
#define BOUNCE_HH  0                        // 128x16 fp16 = 4KB
#define BOUNCE_HF  4096                     // 128x16 f32 = 8KB (final step only)

static __device__ __forceinline__ uint32_t sw128(uint32_t x) { return x ^ ((x >> 3) & 0x70); }

// ---- global scratch (no cudaMalloc allowed) ----
__device__ __half g_hh[2][Bn][512];          // h (fp16), ping-pong, [batch][hidden]
__device__ float g_seqT[Tn][Bn];
__device__ float g_hf[Bn][512];              // final fp32 h for MLP head
__device__ unsigned g_count = 0;
__device__ volatile unsigned g_gen = 0;

__device__ __forceinline__ uint32_t smem_u32(const void* p) {
    uint32_t a;
    asm("{ .reg .u64 t; cvta.to.shared.u64 t, %1; cvt.u32.u64 %0, t; }" : "=r"(a) : "l"(p));
    return a;
}
__device__ __forceinline__ void ldsm_x4(uint32_t* r, uint32_t addr) {
    asm volatile("ldmatrix.sync.aligned.m8n8.x4.shared.b16 {%0,%1,%2,%3}, [%4];"
                 : "=r"(r[0]), "=r"(r[1]), "=r"(r[2]), "=r"(r[3]) : "r"(addr));
}
__device__ __forceinline__ void ldsm_x4_t(uint32_t* r, uint32_t addr) {
    asm volatile("ldmatrix.sync.aligned.m8n8.x4.trans.shared.b16 {%0,%1,%2,%3}, [%4];"
                 : "=r"(r[0]), "=r"(r[1]), "=r"(r[2]), "=r"(r[3]) : "r"(addr));
}
__device__ __forceinline__ void mma_f16(float* d, const uint32_t* a, const uint32_t* b) {
    asm volatile(
        "mma.sync.aligned.m16n8k16.row.col.f32.f16.f16.f32 "
        "{%0,%1,%2,%3}, {%4,%5,%6,%7}, {%8,%9}, {%0,%1,%2,%3};"
        : "+f"(d[0]), "+f"(d[1]), "+f"(d[2]), "+f"(d[3])
        : "r"(a[0]), "r"(a[1]), "r"(a[2]), "r"(a[3]), "r"(b[0]), "r"(b[1]));
}
__device__ __forceinline__ void cp16(uint32_t dst, const void* src) {
    asm volatile("cp.async.cg.shared.global [%0], [%1], 16;"
                 :: "r"(dst), "l"(__cvta_generic_to_global(src)) : "memory");
}
__device__ __forceinline__ void cp_commit() {
    asm volatile("cp.async.commit_group;" ::: "memory");
}
__device__ __forceinline__ void cp_wait0() {
    asm volatile("cp.async.wait_group 0;" ::: "memory");
}

__device__ __forceinline__ void grid_sync(unsigned target) {
    __syncthreads();
    if (threadIdx.x == 0) {
        __threadfence();
        unsigned old = atomicAdd(&g_count, 1u);
        if (old == NBLK - 1) {
            g_count = 0;
            __threadfence();
            g_gen = target;
        } else {
            while (g_gen != target) { }
            __threadfence();
        }
    }
    __syncthreads();
}

__device__ __forceinline__ float sigf(float x)  { return __fdividef(1.0f, 1.0f + __expf(-x)); }
__device__ __forceinline__ float tanhf_(float x){ return __fdividef(2.0f, 1.0f + __expf(-2.0f * x)) - 1.0f; }

__global__ __launch_bounds__(NTHR, 1)
void lstm_tc(const float* __restrict__ seq,
             const float* __restrict__ Wih,
             const float* __restrict__ Whh,
             const float* __restrict__ bih,
             const float* __restrict__ bhh)
{
    extern __shared__ char smem[];
    __shared__ unsigned s_base;
    const uint32_t sb = smem_u32(smem);
    const int tid  = threadIdx.x;
    const int w    = tid >> 5;
    const int lane = tid & 31;
    const int bi   = blockIdx.x >> 5;   // batch tile 0..3
    const int ji   = blockIdx.x & 31;   // hidden-slice tile 0..31 (16 units each)
    const int b0   = bi * 128;
    const int j0   = ji * 16;

    if (tid == 0) s_base = g_gen;

    // ---- W_hh tile -> SMEM, fp16 (single product), k-major [k][n], SW128 swizzle ----
    // local col n = jl*4+g  <->  global W row = g*512 + j0 + jl
    for (int idx = tid; idx < 64 * 512; idx += NTHR) {
        int n = idx >> 9, k = idx & 511;
        int row = (n & 3) * 512 + j0 + (n >> 2);
        float wv = Whh[(size_t)row * 512 + k];
        uint32_t so = sw128((uint32_t)k * 128 + n * 2);
        *(__half*)(smem + OFF_W + so) = __float2half_rn(wv);
    }
    if (tid < 64) {
        int jl = tid >> 2, g = tid & 3;
        int row = g * 512 + j0 + jl;
        ((float*)(smem + OFF_WIH))[tid]  = Wih[row];
        ((float*)(smem + OFF_BIAS))[tid] = bih[row] + bhh[row];
    }
    // zero h0 (buffer 0) and transpose sequence
    {
        int base = blockIdx.x * 2048;
        #pragma unroll
        for (int i = 0; i < 4; ++i) {
            int idx = base + i * NTHR + tid;
            ((__half*)g_hh)[idx] = __float2half_rn(0.0f);
            int b = idx >> 9, t = idx & 511;
            g_seqT[t][b] = seq[idx];
        }
    }
    grid_sync(s_base + 1);
    const unsigned base_gen = s_base;

    // ---- per-lane constants ----
    const int wm = w & 3;                // batch quadrant of warp (m32)
    const int wn = w >> 2;               // gate-col quadrant (n16)
    const int l15 = lane & 15;
    const int lb  = lane >> 4;
    const uint32_t a_row  = (uint32_t)(wm * 32 + l15);
    const uint32_t a_xm   = a_row & 7;
    const uint32_t a_base = sb + a_row * 128;
    const uint32_t b_col16 = (uint32_t)(((wn * 2 + lb) ^ (l15 & 7)));
    const uint32_t b_base  = sb + OFF_W + (uint32_t)l15 * 128 + b_col16 * 16;

    // staging (cp.async dst): thread -> row tid>>2, 32B quarter tid&3
    const int sm_r = tid >> 2, sq = tid & 3;
    const uint32_t sts_off  = sw128((uint32_t)sm_r * 128 + sq * 32);
    const uint32_t sts_off2 = sts_off ^ 16;  // sw128(x+16) == sw128(x) ^ 16 (bit4 of raw x is 0)

    const float* wih_s  = (const float*)(smem + OFF_WIH);
    const float* bias_s = (const float*)(smem + OFF_BIAS);
    float bw_a[2], bw_b[2], wi_a[2], wi_b[2];
    #pragma unroll
    for (int nt = 0; nt < 2; ++nt) {
        int ca = wn * 16 + nt * 8 + (lane & 3) * 2;
        bw_a[nt] = bias_s[ca];     bw_b[nt] = bias_s[ca + 1];
        wi_a[nt] = wih_s[ca];      wi_b[nt] = wih_s[ca + 1];
    }
    const int q = lane & 1;
    const int rowm0 = wm * 32 + (lane >> 2);
    float cst[4] = {0.f, 0.f, 0.f, 0.f};

    for (int t = 0; t < Tn; ++t) {
        const int rb = t & 1, nb = rb ^ 1;

        // init accumulators with bias + x*W_ih (mma accumulates on top)
        float acc[2][2][4];
        #pragma unroll
        for (int mt = 0; mt < 2; ++mt) {
            float svA = g_seqT[t][b0 + rowm0 + mt * 16];
            float svB = g_seqT[t][b0 + rowm0 + mt * 16 + 8];
            #pragma unroll
            for (int nt = 0; nt < 2; ++nt) {
                acc[mt][nt][0] = fmaf(svA, wi_a[nt], bw_a[nt]);
                acc[mt][nt][1] = fmaf(svA, wi_b[nt], bw_b[nt]);
                acc[mt][nt][2] = fmaf(svB, wi_a[nt], bw_a[nt]);
                acc[mt][nt][3] = fmaf(svB, wi_b[nt], bw_b[nt]);
            }
        }

        // stage chunk 0 into buf 0 (h for this step is globally visible after barrier)
        {
            const __half* sh = &g_hh[rb][b0 + sm_r][sq * 16];
            cp16(sb + OFF_H(0) + sts_off,  sh);
            cp16(sb + OFF_H(0) + sts_off2, sh + 8);
            cp_commit();
        }

        #pragma unroll 1
        for (int kc = 0; kc < 8; ++kc) {
            cp_wait0();
            __syncthreads();      // chunk kc visible to all; prior reads of other buf done
            if (kc < 7) {
                const int nbuf = (kc + 1) & 1;
                const __half* sh = &g_hh[rb][b0 + sm_r][(kc + 1) * 64 + sq * 16];
                cp16(sb + OFF_H(nbuf) + sts_off,  sh);
                cp16(sb + OFF_H(nbuf) + sts_off2, sh + 8);
                cp_commit();
            }

            const uint32_t abuf = a_base + OFF_H(kc & 1);
            const uint32_t bk   = b_base + (uint32_t)kc * 8192;
            #pragma unroll
            for (int kq = 0; kq < 4; ++kq) {
                const uint32_t acol = (uint32_t)(((kq * 2 + lb) ^ a_xm)) << 4;
                uint32_t ah0[4], ah1[4], bh[4];
                ldsm_x4(ah0, abuf + acol);                       // A m16 #0, k16
                ldsm_x4(ah1, abuf + 2048 + acol);                // A m16 #1
                ldsm_x4_t(bh, bk + (uint32_t)kq * 2048);         // W (k16 x n16)
                // 4 HMMA: single product (W fp16, h fp16)
                mma_f16(acc[0][0], ah0, bh);   mma_f16(acc[0][1], ah0, bh + 2);
                mma_f16(acc[1][0], ah1, bh);   mma_f16(acc[1][1], ah1, bh + 2);
            }
        }

        __syncthreads();   // all chunk reads done -> buf0 reusable as bounce

        // ---- LSTM cell epilogue: lane pairs exchange (i,f)<->(g,o) ----
        #pragma unroll
        for (int mt = 0; mt < 2; ++mt) {
            #pragma unroll
            for (int nt = 0; nt < 2; ++nt) {
                float x0 = __shfl_xor_sync(0xffffffffu, acc[mt][nt][0], 1);
                float x1 = __shfl_xor_sync(0xffffffffu, acc[mt][nt][1], 1);
                float x2 = __shfl_xor_sync(0xffffffffu, acc[mt][nt][2], 1);
                float x3 = __shfl_xor_sync(0xffffffffu, acc[mt][nt][3], 1);
                float gi, gf, gg, go;
                int rowl;
                if (q == 0) { gi = acc[mt][nt][0]; gf = acc[mt][nt][1]; gg = x0; go = x1;
                              rowl = rowm0 + mt * 16; }
                else        { gi = x2; gf = x3; gg = acc[mt][nt][2]; go = acc[mt][nt][3];
                              rowl = rowm0 + mt * 16 + 8; }
                const int ci = mt * 2 + nt;
                cst[ci] = sigf(gf) * cst[ci] + sigf(gi) * tanhf_(gg);
                float h = sigf(go) * tanhf_(cst[ci]);
                int ul = wn * 4 + nt * 2 + ((lane & 3) >> 1);
                *(__half*)(smem + BOUNCE_HH + rowl * 32 + ul * 2) = __float2half_rn(h);
                if (t == Tn - 1)
                    *(float*)(smem + BOUNCE_HF + rowl * 64 + ul * 4) = h;
            }
        }
        __syncthreads();
        // coalesced write-out of this CTA's 128x16 h slice
        if (t < Tn - 1) {
            unsigned long long hv = *(unsigned long long*)(smem + BOUNCE_HH + sm_r * 32 + sq * 8);
            *(unsigned long long*)&g_hh[nb][b0 + sm_r][j0 + sq * 4] = hv;
        } else {
            float4 f4 = *(float4*)(smem + BOUNCE_HF + sm_r * 64 + sq * 16);
            *(float4*)&g_hf[b0 + sm_r][j0 + sq * 4] = f4;
        }
        grid_sync(base_gen + 2 + t);
    }
}

__global__ __launch_bounds__(256)
void mlp_head(const float* __restrict__ fc1w, const float* __restrict__ fc1b,
              const float* __restrict__ fc2w, const float* __restrict__ fc2b,
              float* __restrict__ out)
{
    __shared__ float hcol[512];
    __shared__ float z[256];
    const int b = blockIdx.x;
    const int tid = threadIdx.x;

    hcol[tid]       = g_hf[b][tid];
    hcol[tid + 256] = g_hf[b][tid + 256];
    __syncthreads();

    float acc = fc1b[tid];
    const float4* w4 = (const float4*)(fc1w + (size_t)tid * 512);
    const float4* h4 = (const float4*)hcol;
    #pragma unroll 4
    for (int k = 0; k < 128; ++k) {
        float4 wv = w4[k], hv = h4[k];
        acc = fmaf(wv.x, hv.x, acc); acc = fmaf(wv.y, hv.y, acc);
        acc = fmaf(wv.z, hv.z, acc); acc = fmaf(wv.w, hv.w, acc);
    }
    z[tid] = fmaxf(acc, 0.0f);
    __syncthreads();

    if (tid < 28) {
        float o = fc2b[tid];
        const float4* w4b = (const float4*)(fc2w + (size_t)tid * 256);
        const float4* z4  = (const float4*)z;
        #pragma unroll 4
        for (int k = 0; k < 64; ++k) {
            float4 wv = w4b[k], zz = z4[k];
            o = fmaf(wv.x, zz.x, o); o = fmaf(wv.y, zz.y, o);
            o = fmaf(wv.z, zz.z, o); o = fmaf(wv.w, zz.w, o);
        }
        out[b * 28 + tid] = o;
    }
}

extern "C" void kernel_launch(void* const* d_in, const int* in_sizes, int n_in,
                              void* d_out, int out_size) {
    const float* seq  = (const float*)d_in[0];
    const float* Wih  = (const float*)d_in[1];
    const float* Whh  = (const float*)d_in[2];
    const float* bih  = (const float*)d_in[3];
    const float* bhh  = (const float*)d_in[4];
    const float* fc1w = (const float*)d_in[5];
    const float* fc1b = (const float*)d_in[6];
    const float* fc2w = (const float*)d_in[7];
    const float* fc2b = (const float*)d_in[8];
    float* out = (float*)d_out;

    cudaFuncSetAttribute(lstm_tc, cudaFuncAttributeMaxDynamicSharedMemorySize, SMEM_BYTES);
    lstm_tc<<<NBLK, NTHR, SMEM_BYTES>>>(seq, Wih, Whh, bih, bhh);
    mlp_head<<<Bn, 256>>>(fc1w, fc1b, fc2w, fc2b, out);
}